// round 1
// baseline (speedup 1.0000x reference)
#include <cuda_runtime.h>
#include <cuda_bf16.h>

// ---------------------------------------------------------------------------
// GAT layer with edge softmax — algebraically reduced.
//
//   u[n]  = x[n] @ W_in[:64]              (N x 64)
//   v[n]  = x[n] @ W_in[64:] + b_in       (N x 64)
//   p[n]  = x[n] @ W_out + b_out          (N x 64)
//   e     = leaky(u[src]+v[tgt]) . a_w + a_b       (per edge, scalar)
//   S[n]  = sum_{tgt=n} exp(e) + eps
//   out[n]= leaky( ((S-eps)/S) * p[n] )
//
// The per-edge vector aggregation collapses because x[tgt] @ W_out depends
// only on tgt: sum(alpha * p[tgt]) over edges with tgt=n == (sum alpha) * p[n].
// ---------------------------------------------------------------------------

#define DI 64
#define NMAX 100000
#define XPAD 40   // xsT row pad (floats); k*XPAD*4 multiple of 16 for float4 loads

__device__ float g_u[(size_t)NMAX * DI];
__device__ float g_v[(size_t)NMAX * DI];
__device__ float g_p[(size_t)NMAX * DI];
__device__ float g_S[NMAX];

typedef unsigned long long ull;

__device__ __forceinline__ ull pk2(float a) {
    ull r; asm("mov.b64 %0, {%1, %1};" : "=l"(r) : "f"(a)); return r;
}
__device__ __forceinline__ void fma2(ull& d, ull a, ull b) {
    asm("fma.rn.f32x2 %0, %1, %2, %0;" : "+l"(d) : "l"(a), "l"(b));
}
__device__ __forceinline__ float2 unpk(ull v) {
    float2 r; asm("mov.b64 {%0, %1}, %2;" : "=f"(r.x), "=f"(r.y) : "l"(v)); return r;
}
__device__ __forceinline__ float lrelu(float x) { return x >= 0.0f ? x : 0.01f * x; }

// ---------------------------------------------------------------------------
// Kernel A: fused node GEMM  [N,64] @ [64,192] -> u | v | p
// Block = 256 threads, tile = 32 nodes x 192 cols, k split in 2 halves of 32.
// Each thread: 4 nodes x 6 cols as 12 packed f32x2 accumulators.
// ---------------------------------------------------------------------------
__global__ void __launch_bounds__(256) precompute_kernel(
    const float* __restrict__ x, const float* __restrict__ W_in,
    const float* __restrict__ b_in, const float* __restrict__ W_out,
    const float* __restrict__ b_out, int n)
{
    __shared__ float WsH[32 * 192];       // 24 KB: half of combined weights
    __shared__ float xsT[64 * XPAD];      // 10 KB: x tile, transposed [k][node]

    const int tid  = threadIdx.x;
    const int base = blockIdx.x * 32;

    for (int idx = tid; idx < 32 * 64; idx += 256) {
        int node = idx >> 6, k = idx & 63;
        int gn = base + node;
        xsT[k * XPAD + node] = (gn < n) ? x[(size_t)gn * 64 + k] : 0.0f;
    }

    ull acc[12];
#pragma unroll
    for (int i = 0; i < 12; i++) acc[i] = 0ull;

    const int tx = tid & 31;   // col group: cols [6*tx, 6*tx+6)
    const int ty = tid >> 5;   // node group: nodes [4*ty, 4*ty+4)

    for (int kk = 0; kk < 64; kk += 32) {
        __syncthreads();
        for (int idx = tid; idx < 32 * 192; idx += 256) {
            int k2 = idx / 192, j = idx - k2 * 192;
            int k = kk + k2;
            float wv;
            if (j < 64)       wv = W_in[k * 64 + j];
            else if (j < 128) wv = W_in[(64 + k) * 64 + (j - 64)];
            else              wv = W_out[k * 64 + (j - 128)];
            WsH[idx] = wv;
        }
        __syncthreads();

#pragma unroll 8
        for (int k2 = 0; k2 < 32; k2++) {
            const int k = kk + k2;
            const float4 a4 = *(const float4*)&xsT[k * XPAD + 4 * ty];
            const ull* wp = (const ull*)&WsH[k2 * 192 + 6 * tx];
            const ull b0 = wp[0], b1 = wp[1], b2 = wp[2];
            const ull a0 = pk2(a4.x), a1 = pk2(a4.y), a2 = pk2(a4.z), a3 = pk2(a4.w);
            fma2(acc[0], a0, b0);  fma2(acc[1], a0, b1);  fma2(acc[2],  a0, b2);
            fma2(acc[3], a1, b0);  fma2(acc[4], a1, b1);  fma2(acc[5],  a1, b2);
            fma2(acc[6], a2, b0);  fma2(acc[7], a2, b1);  fma2(acc[8],  a2, b2);
            fma2(acc[9], a3, b0);  fma2(acc[10],a3, b1);  fma2(acc[11], a3, b2);
        }
    }

#pragma unroll
    for (int i = 0; i < 4; i++) {
        const int gn = base + 4 * ty + i;
        if (gn >= n) break;
#pragma unroll
        for (int c = 0; c < 3; c++) {
            float2 r = unpk(acc[i * 3 + c]);
            const int j = 6 * tx + 2 * c;
            if (j < 64) {
                *(float2*)&g_u[(size_t)gn * 64 + j] = r;
            } else if (j < 128) {
                const int jj = j - 64;
                r.x += b_in[jj]; r.y += b_in[jj + 1];
                *(float2*)&g_v[(size_t)gn * 64 + jj] = r;
            } else {
                const int jj = j - 128;
                r.x += b_out[jj]; r.y += b_out[jj + 1];
                *(float2*)&g_p[(size_t)gn * 64 + jj] = r;
            }
        }
    }
}

// ---------------------------------------------------------------------------
// Kernel Z: zero the segment accumulator
// ---------------------------------------------------------------------------
__global__ void zero_kernel(int n) {
    int i = blockIdx.x * blockDim.x + threadIdx.x;
    if (i < n) g_S[i] = 0.0f;
}

// ---------------------------------------------------------------------------
// Kernel B: warp-per-edge logit + exp + atomic segment sum
// ---------------------------------------------------------------------------
#define EDGES_PER_WARP 4

__global__ void __launch_bounds__(256) edge_kernel(
    const int* __restrict__ src, const int* __restrict__ tgt,
    const float* __restrict__ a_w, const float* __restrict__ a_b, int E)
{
    const int lane = threadIdx.x & 31;
    const int warp = (blockIdx.x * 256 + threadIdx.x) >> 5;
    const float2 aw = *(const float2*)&a_w[2 * lane];
    const float ab = a_b[0];

    int e = warp * EDGES_PER_WARP;
#pragma unroll
    for (int i = 0; i < EDGES_PER_WARP; i++, e++) {
        if (e >= E) return;
        const int s = __ldg(&src[e]);
        const int t = __ldg(&tgt[e]);
        const float2 uu = *(const float2*)&g_u[(size_t)s * 64 + 2 * lane];
        const float2 vv = *(const float2*)&g_v[(size_t)t * 64 + 2 * lane];
        const float w0 = lrelu(uu.x + vv.x);
        const float w1 = lrelu(uu.y + vv.y);
        float part = fmaf(w0, aw.x, w1 * aw.y);
        part += __shfl_xor_sync(0xffffffffu, part, 16);
        part += __shfl_xor_sync(0xffffffffu, part, 8);
        part += __shfl_xor_sync(0xffffffffu, part, 4);
        part += __shfl_xor_sync(0xffffffffu, part, 2);
        part += __shfl_xor_sync(0xffffffffu, part, 1);
        if (lane == 0) atomicAdd(&g_S[t], __expf(part + ab));
    }
}

// ---------------------------------------------------------------------------
// Kernel C: out = leaky( (S/(S+eps)) * p )   [S here is the raw sum]
// ---------------------------------------------------------------------------
__global__ void __launch_bounds__(256) finalize_kernel(float* __restrict__ out, int n) {
    const int gid = blockIdx.x * 256 + threadIdx.x;
    if (gid >= n * 16) return;
    const int node = gid >> 4;
    const int j = (gid & 15) << 2;
    const float S = g_S[node];
    const float f = S / (S + 1e-6f);
    float4 p = *(const float4*)&g_p[(size_t)node * 64 + j];
    float4 o;
    o.x = lrelu(f * p.x);
    o.y = lrelu(f * p.y);
    o.z = lrelu(f * p.z);
    o.w = lrelu(f * p.w);
    *(float4*)&out[(size_t)node * 64 + j] = o;
}

// ---------------------------------------------------------------------------
extern "C" void kernel_launch(void* const* d_in, const int* in_sizes, int n_in,
                              void* d_out, int out_size)
{
    const float* x     = (const float*)d_in[0];
    const int*   src   = (const int*)  d_in[1];
    const int*   tgt   = (const int*)  d_in[2];
    const float* W_in  = (const float*)d_in[3];
    const float* b_in  = (const float*)d_in[4];
    const float* a_w   = (const float*)d_in[5];
    const float* a_b   = (const float*)d_in[6];
    const float* W_out = (const float*)d_in[7];
    const float* b_out = (const float*)d_in[8];
    float* out = (float*)d_out;

    const int N = in_sizes[0] / DI;
    const int E = in_sizes[1];

    const int gemm_blocks = (N + 31) / 32;
    precompute_kernel<<<gemm_blocks, 256>>>(x, W_in, b_in, W_out, b_out, N);

    zero_kernel<<<(N + 1023) / 1024, 1024>>>(N);

    const int warps = (E + EDGES_PER_WARP - 1) / EDGES_PER_WARP;
    const int edge_blocks = (warps + 7) / 8;   // 8 warps per 256-thread block
    edge_kernel<<<edge_blocks, 256>>>(src, tgt, a_w, a_b, E);

    finalize_kernel<<<(N * 16 + 255) / 256, 256>>>(out, N);
}

// round 2
// speedup vs baseline: 1.2614x; 1.2614x over previous
#include <cuda_runtime.h>
#include <cuda_bf16.h>

// ---------------------------------------------------------------------------
// GAT layer with edge softmax — algebraically reduced.
//
//   u[n]  = x[n] @ W_in[:64]              (N x 64)   -> bf16
//   v[n]  = x[n] @ W_in[64:] + b_in       (N x 64)   -> bf16
//   p[n]  = x[n] @ W_out + b_out          (N x 64)   -> fp32
//   e     = leaky(u[src]+v[tgt]) . a_w + a_b         (per edge, scalar)
//   S[n]  = sum_{tgt=n} exp(e)
//   out[n]= leaky( (S/(S+eps)) * p[n] )
//
// Per-edge vector aggregation collapses because x[tgt]@W_out depends only on
// tgt. Output depends on logits only via eps/S (~1e-6), so u/v in bf16 is
// numerically free; p stays fp32 because out ~= leaky(p).
// ---------------------------------------------------------------------------

#define DI 64
#define NMAX 100000
#define XPAD 40   // xsT row pad (floats)

__device__ __nv_bfloat16 g_u[(size_t)NMAX * DI];
__device__ __nv_bfloat16 g_v[(size_t)NMAX * DI];
__device__ float g_p[(size_t)NMAX * DI];
__device__ float g_S[NMAX];

typedef unsigned long long ull;

__device__ __forceinline__ ull pk2(float a) {
    ull r; asm("mov.b64 %0, {%1, %1};" : "=l"(r) : "f"(a)); return r;
}
__device__ __forceinline__ void fma2(ull& d, ull a, ull b) {
    asm("fma.rn.f32x2 %0, %1, %2, %0;" : "+l"(d) : "l"(a), "l"(b));
}
__device__ __forceinline__ float2 unpk(ull v) {
    float2 r; asm("mov.b64 {%0, %1}, %2;" : "=f"(r.x), "=f"(r.y) : "l"(v)); return r;
}
__device__ __forceinline__ float lrelu(float x) { return x >= 0.0f ? x : 0.01f * x; }

// ---------------------------------------------------------------------------
// Kernel A: fused node GEMM  [N,64] @ [64,192] -> u(bf16) | v(bf16) | p(fp32)
// Also zeroes g_S (folded former zero_kernel).
// Block = 256 threads, tile = 32 nodes x 192 cols, k split in 2 halves of 32.
// Each thread: 4 nodes x 6 cols as 12 packed f32x2 accumulators.
// ---------------------------------------------------------------------------
__global__ void __launch_bounds__(256) precompute_kernel(
    const float* __restrict__ x, const float* __restrict__ W_in,
    const float* __restrict__ b_in, const float* __restrict__ W_out,
    const float* __restrict__ b_out, int n)
{
    __shared__ float WsH[32 * 192];       // 24 KB: half of combined weights
    __shared__ float xsT[64 * XPAD];      // 10 KB: x tile, transposed [k][node]

    const int tid  = threadIdx.x;
    const int base = blockIdx.x * 32;

    // fold: zero the segment-sum accumulator
    {
        const int zi = blockIdx.x * 256 + tid;
        if (zi < n) g_S[zi] = 0.0f;
    }

    for (int idx = tid; idx < 32 * 64; idx += 256) {
        int node = idx >> 6, k = idx & 63;
        int gn = base + node;
        xsT[k * XPAD + node] = (gn < n) ? x[(size_t)gn * 64 + k] : 0.0f;
    }

    ull acc[12];
#pragma unroll
    for (int i = 0; i < 12; i++) acc[i] = 0ull;

    const int tx = tid & 31;   // col group: cols [6*tx, 6*tx+6)
    const int ty = tid >> 5;   // node group: nodes [4*ty, 4*ty+4)

    for (int kk = 0; kk < 64; kk += 32) {
        __syncthreads();
        for (int idx = tid; idx < 32 * 192; idx += 256) {
            int k2 = idx / 192, j = idx - k2 * 192;
            int k = kk + k2;
            float wv;
            if (j < 64)       wv = W_in[k * 64 + j];
            else if (j < 128) wv = W_in[(64 + k) * 64 + (j - 64)];
            else              wv = W_out[k * 64 + (j - 128)];
            WsH[idx] = wv;
        }
        __syncthreads();

#pragma unroll 8
        for (int k2 = 0; k2 < 32; k2++) {
            const int k = kk + k2;
            const float4 a4 = *(const float4*)&xsT[k * XPAD + 4 * ty];
            const ull* wp = (const ull*)&WsH[k2 * 192 + 6 * tx];
            const ull b0 = wp[0], b1 = wp[1], b2 = wp[2];
            const ull a0 = pk2(a4.x), a1 = pk2(a4.y), a2 = pk2(a4.z), a3 = pk2(a4.w);
            fma2(acc[0], a0, b0);  fma2(acc[1], a0, b1);  fma2(acc[2],  a0, b2);
            fma2(acc[3], a1, b0);  fma2(acc[4], a1, b1);  fma2(acc[5],  a1, b2);
            fma2(acc[6], a2, b0);  fma2(acc[7], a2, b1);  fma2(acc[8],  a2, b2);
            fma2(acc[9], a3, b0);  fma2(acc[10],a3, b1);  fma2(acc[11], a3, b2);
        }
    }

#pragma unroll
    for (int i = 0; i < 4; i++) {
        const int gn = base + 4 * ty + i;
        if (gn >= n) break;
#pragma unroll
        for (int c = 0; c < 3; c++) {
            float2 r = unpk(acc[i * 3 + c]);
            const int j = 6 * tx + 2 * c;
            if (j < 64) {
                *(__nv_bfloat162*)&g_u[(size_t)gn * 64 + j] = __float22bfloat162_rn(r);
            } else if (j < 128) {
                const int jj = j - 64;
                r.x += b_in[jj]; r.y += b_in[jj + 1];
                *(__nv_bfloat162*)&g_v[(size_t)gn * 64 + jj] = __float22bfloat162_rn(r);
            } else {
                const int jj = j - 128;
                r.x += b_out[jj]; r.y += b_out[jj + 1];
                *(float2*)&g_p[(size_t)gn * 64 + jj] = r;
            }
        }
    }
}

// ---------------------------------------------------------------------------
// Kernel B: half-warp-per-edge logit + exp + atomic segment sum
// 16 lanes per edge, 4 bf16 features per lane (8B loads), 4-step shuffle.
// ---------------------------------------------------------------------------
#define EDGES_PER_WARP 8   // 2 per pass * 4 passes

__global__ void __launch_bounds__(256) edge_kernel(
    const int* __restrict__ src, const int* __restrict__ tgt,
    const float* __restrict__ a_w, const float* __restrict__ a_b, int E)
{
    const int lane = threadIdx.x & 31;
    const int half = lane >> 4;       // which edge of the pair
    const int hl   = lane & 15;       // lane within half: cols [4*hl, 4*hl+4)
    const int warp = (blockIdx.x * 256 + threadIdx.x) >> 5;

    const float4 aw = *(const float4*)&a_w[4 * hl];
    const float ab = a_b[0];

    const int e0 = warp * EDGES_PER_WARP + half;
#pragma unroll
    for (int i = 0; i < EDGES_PER_WARP / 2; i++) {
        const int e = e0 + 2 * i;
        const bool valid = (e < E);
        const int ee = valid ? e : (E - 1);
        const int s = __ldg(&src[ee]);
        const int t = __ldg(&tgt[ee]);

        // 4 bf16 each from u[s] and v[t]
        const uint2 ur = *(const uint2*)&g_u[(size_t)s * 64 + 4 * hl];
        const uint2 vr = *(const uint2*)&g_v[(size_t)t * 64 + 4 * hl];
        const float2 u0 = __bfloat1622float2(*(const __nv_bfloat162*)&ur.x);
        const float2 u1 = __bfloat1622float2(*(const __nv_bfloat162*)&ur.y);
        const float2 v0 = __bfloat1622float2(*(const __nv_bfloat162*)&vr.x);
        const float2 v1 = __bfloat1622float2(*(const __nv_bfloat162*)&vr.y);

        float part;
        part  = lrelu(u0.x + v0.x) * aw.x;
        part  = fmaf(lrelu(u0.y + v0.y), aw.y, part);
        part  = fmaf(lrelu(u1.x + v1.x), aw.z, part);
        part  = fmaf(lrelu(u1.y + v1.y), aw.w, part);

        part += __shfl_xor_sync(0xffffffffu, part, 8);
        part += __shfl_xor_sync(0xffffffffu, part, 4);
        part += __shfl_xor_sync(0xffffffffu, part, 2);
        part += __shfl_xor_sync(0xffffffffu, part, 1);

        if (hl == 0 && valid) atomicAdd(&g_S[t], __expf(part + ab));
    }
}

// ---------------------------------------------------------------------------
// Kernel C: out = leaky( (S/(S+eps)) * p )
// ---------------------------------------------------------------------------
__global__ void __launch_bounds__(256) finalize_kernel(float* __restrict__ out, int n) {
    const int gid = blockIdx.x * 256 + threadIdx.x;
    if (gid >= n * 16) return;
    const int node = gid >> 4;
    const int j = (gid & 15) << 2;
    const float S = g_S[node];
    const float f = S / (S + 1e-6f);
    float4 p = *(const float4*)&g_p[(size_t)node * 64 + j];
    float4 o;
    o.x = lrelu(f * p.x);
    o.y = lrelu(f * p.y);
    o.z = lrelu(f * p.z);
    o.w = lrelu(f * p.w);
    *(float4*)&out[(size_t)node * 64 + j] = o;
}

// ---------------------------------------------------------------------------
extern "C" void kernel_launch(void* const* d_in, const int* in_sizes, int n_in,
                              void* d_out, int out_size)
{
    const float* x     = (const float*)d_in[0];
    const int*   src   = (const int*)  d_in[1];
    const int*   tgt   = (const int*)  d_in[2];
    const float* W_in  = (const float*)d_in[3];
    const float* b_in  = (const float*)d_in[4];
    const float* a_w   = (const float*)d_in[5];
    const float* a_b   = (const float*)d_in[6];
    const float* W_out = (const float*)d_in[7];
    const float* b_out = (const float*)d_in[8];
    float* out = (float*)d_out;

    const int N = in_sizes[0] / DI;
    const int E = in_sizes[1];

    const int gemm_blocks = (N + 31) / 32;   // 3125 blocks also zero g_S (3125*256 > N)
    precompute_kernel<<<gemm_blocks, 256>>>(x, W_in, b_in, W_out, b_out, N);

    const int warps = (E + EDGES_PER_WARP - 1) / EDGES_PER_WARP;
    const int edge_blocks = (warps + 7) / 8;   // 8 warps per 256-thread block
    edge_kernel<<<edge_blocks, 256>>>(src, tgt, a_w, a_b, E);

    finalize_kernel<<<(N * 16 + 255) / 256, 256>>>(out, N);
}

// round 4
// speedup vs baseline: 2.2270x; 1.7655x over previous
#include <cuda_runtime.h>
#include <cuda_bf16.h>
#include <cstdint>

// ---------------------------------------------------------------------------
// GAT layer with edge softmax — algebraically reduced + HMMA (mma.sync) precompute.
//
//   u[n]  = x[n] @ W_in[:64]              (N x 64)   -> bf16   (plain bf16 MMA)
//   v[n]  = x[n] @ W_in[64:] + b_in       (N x 64)   -> bf16   (plain bf16 MMA)
//   p[n]  = x[n] @ W_out + b_out          (N x 64)   -> fp32   (3-term bf16-split MMA)
//   e     = leaky(u[src]+v[tgt]) . a_w + a_b         (per edge, scalar)
//   S[n]  = sum_{tgt=n} exp(e)
//   out[n]= leaky( (S/(S+eps)) * p[n] )
//
// tcgen05 is unavailable (harness PTX targets compute_103, no 'a' features),
// so the tensor pipe is driven with mma.sync.m16n8k16.bf16.
// ---------------------------------------------------------------------------

#define DI 64
#define NMAX 100000

__device__ __nv_bfloat16 g_u[(size_t)NMAX * DI];
__device__ __nv_bfloat16 g_v[(size_t)NMAX * DI];
__device__ float g_p[(size_t)NMAX * DI];
__device__ float g_S[NMAX];

__device__ __forceinline__ float lrelu(float x) { return x >= 0.0f ? x : 0.01f * x; }

__device__ __forceinline__ uint32_t smem_u32(const void* p) {
    uint32_t a;
    asm("{ .reg .u64 t; cvta.to.shared.u64 t, %1; cvt.u32.u64 %0, t; }" : "=r"(a) : "l"(p));
    return a;
}

#define MMA_BF16(c, a, b) \
    asm volatile("mma.sync.aligned.m16n8k16.row.col.f32.bf16.bf16.f32 " \
        "{%0,%1,%2,%3}, {%4,%5,%6,%7}, {%8,%9}, {%0,%1,%2,%3};" \
        : "+f"((c)[0]), "+f"((c)[1]), "+f"((c)[2]), "+f"((c)[3]) \
        : "r"((a)[0]), "r"((a)[1]), "r"((a)[2]), "r"((a)[3]), \
          "r"((b)[0]), "r"((b)[1]))

#define LDSM4(r, addr) \
    asm volatile("ldmatrix.sync.aligned.m8n8.x4.shared.b16 {%0,%1,%2,%3}, [%4];" \
        : "=r"((r)[0]), "=r"((r)[1]), "=r"((r)[2]), "=r"((r)[3]) : "r"(addr))

// smem A tiles: 128 rows x 64 bf16, row stride 144 bytes (16B aligned, bank-staggered)
#define A_STRIDE 144
#define A_BYTES  (128 * A_STRIDE)      // 18432

// combined weight accessor: col j in [0,192): 0..63 u (W_in top), 64..127 v (W_in bottom), 128..191 p (W_out)
__device__ __forceinline__ float Wsel(const float* __restrict__ W_in,
                                      const float* __restrict__ W_out, int k, int j) {
    if (j < 64)  return W_in[k * 64 + j];
    if (j < 128) return W_in[(64 + k) * 64 + (j - 64)];
    return W_out[k * 64 + (j - 128)];
}

__device__ __forceinline__ uint32_t pack_bf16x2(float a, float b) {
    __nv_bfloat162 h = __floats2bfloat162_rn(a, b);
    return *(uint32_t*)&h;
}

// ---------------------------------------------------------------------------
// Kernel A: HMMA node GEMM  [N,64] @ [64,192] -> u(bf16) | v(bf16) | p(fp32)
// 128 nodes per CTA, 256 threads (8 warps). Also zeroes g_S.
// Warp w: uv n8-tiles at cols 16w, 16w+8 (u if w<4 else v), p n8-tile at col 128+8w.
// ---------------------------------------------------------------------------
__global__ void __launch_bounds__(256) precompute_mma(
    const float* __restrict__ x, const float* __restrict__ W_in,
    const float* __restrict__ b_in, const float* __restrict__ W_out,
    const float* __restrict__ b_out, int n)
{
    __shared__ __align__(16) char smem[2 * A_BYTES];   // A_hi | A_lo
    const uint32_t sb = smem_u32(smem);
    const int tid  = threadIdx.x;
    const int w    = tid >> 5;
    const int lane = tid & 31;
    const int g    = lane >> 2;    // fragment group row / B col
    const int t    = lane & 3;     // fragment col-pair index
    const int base = blockIdx.x * 128;

    // fold: zero segment accumulator
    {
        const int zi = blockIdx.x * 256 + tid;
        if (zi < n) g_S[zi] = 0.0f;
    }

    // ---- B fragments in registers (per warp) ----
    // b0 = {W(2t+16s, j), W(2t+1+16s, j)}, b1 = {W(2t+8+16s, j), W(2t+9+16s, j)}, j = j0+g
    uint32_t Buv[2][4][2];     // [uv tile][kstep][b0/b1]
    uint32_t BpH[4][2], BpL[4][2];
#pragma unroll
    for (int tt = 0; tt < 2; tt++) {
        const int j = 16 * w + 8 * tt + g;
#pragma unroll
        for (int s = 0; s < 4; s++) {
            const int k0 = 16 * s + 2 * t;
            Buv[tt][s][0] = pack_bf16x2(Wsel(W_in, W_out, k0,     j), Wsel(W_in, W_out, k0 + 1, j));
            Buv[tt][s][1] = pack_bf16x2(Wsel(W_in, W_out, k0 + 8, j), Wsel(W_in, W_out, k0 + 9, j));
        }
    }
    {
        const int j = 128 + 8 * w + g;
#pragma unroll
        for (int s = 0; s < 4; s++) {
            const int k0 = 16 * s + 2 * t;
            float f00 = Wsel(W_in, W_out, k0,     j), f01 = Wsel(W_in, W_out, k0 + 1, j);
            float f10 = Wsel(W_in, W_out, k0 + 8, j), f11 = Wsel(W_in, W_out, k0 + 9, j);
            __nv_bfloat16 h00 = __float2bfloat16(f00), h01 = __float2bfloat16(f01);
            __nv_bfloat16 h10 = __float2bfloat16(f10), h11 = __float2bfloat16(f11);
            BpH[s][0] = pack_bf16x2(f00, f01);
            BpH[s][1] = pack_bf16x2(f10, f11);
            BpL[s][0] = pack_bf16x2(f00 - __bfloat162float(h00), f01 - __bfloat162float(h01));
            BpL[s][1] = pack_bf16x2(f10 - __bfloat162float(h10), f11 - __bfloat162float(h11));
        }
    }

    // bias preloads
    float bv[2][2];   // v bias (warps 4-7): [tile][col pair]
    if (w >= 4) {
#pragma unroll
        for (int tt = 0; tt < 2; tt++) {
            const int jv = 16 * w + 8 * tt + 2 * t - 64;
            bv[tt][0] = b_in[jv]; bv[tt][1] = b_in[jv + 1];
        }
    }
    const float bo0 = b_out[8 * w + 2 * t];
    const float bo1 = b_out[8 * w + 2 * t + 1];

    // ---- stage x tile as bf16 hi/lo into smem ----
    for (int i = tid; i < 128 * 16; i += 256) {
        const int node = i >> 4, kc = i & 15;     // kc: float4 chunk (4 k values)
        const int gn = base + node;
        float4 xv = make_float4(0.f, 0.f, 0.f, 0.f);
        if (gn < n) xv = *(const float4*)&x[(size_t)gn * 64 + 4 * kc];
        __nv_bfloat16 h0 = __float2bfloat16(xv.x), h1 = __float2bfloat16(xv.y);
        __nv_bfloat16 h2 = __float2bfloat16(xv.z), h3 = __float2bfloat16(xv.w);
        uint2 hi, lo;
        hi.x = pack_bf16x2(xv.x, xv.y);  // note: pack_bf16x2 re-rounds; identical to h0,h1
        hi.y = pack_bf16x2(xv.z, xv.w);
        lo.x = pack_bf16x2(xv.x - __bfloat162float(h0), xv.y - __bfloat162float(h1));
        lo.y = pack_bf16x2(xv.z - __bfloat162float(h2), xv.w - __bfloat162float(h3));
        *(uint2*)(smem + node * A_STRIDE + kc * 8)           = hi;
        *(uint2*)(smem + A_BYTES + node * A_STRIDE + kc * 8) = lo;
    }
    __syncthreads();

    // ---- per-warp MMA + epilogue ----
    // ldmatrix addressing: row = m0 + (lane&15), col bytes = 32s + 16*(lane>>4)
    const int lrow = lane & 15;
    const int lcol = (lane >> 4) * 16;

#pragma unroll 1
    for (int mt = 0; mt < 8; mt++) {
        const int m0 = 16 * mt;
        uint32_t ah[4][4], al[4][4];
#pragma unroll
        for (int s = 0; s < 4; s++) {
            const uint32_t off = (uint32_t)((m0 + lrow) * A_STRIDE + 32 * s + lcol);
            LDSM4(ah[s], sb + off);
            LDSM4(al[s], sb + A_BYTES + off);
        }

        const int node_lo = base + m0 + g;
        const int node_hi = node_lo + 8;

        // uv tiles
#pragma unroll
        for (int tt = 0; tt < 2; tt++) {
            float c[4] = {0.f, 0.f, 0.f, 0.f};
#pragma unroll
            for (int s = 0; s < 4; s++) MMA_BF16(c, ah[s], Buv[tt][s]);
            const int col = 16 * w + 8 * tt + 2 * t;
            if (w < 4) {
                if (node_lo < n) *(uint32_t*)&g_u[(size_t)node_lo * 64 + col] = pack_bf16x2(c[0], c[1]);
                if (node_hi < n) *(uint32_t*)&g_u[(size_t)node_hi * 64 + col] = pack_bf16x2(c[2], c[3]);
            } else {
                const int cv = col - 64;
                if (node_lo < n) *(uint32_t*)&g_v[(size_t)node_lo * 64 + cv] = pack_bf16x2(c[0] + bv[tt][0], c[1] + bv[tt][1]);
                if (node_hi < n) *(uint32_t*)&g_v[(size_t)node_hi * 64 + cv] = pack_bf16x2(c[2] + bv[tt][0], c[3] + bv[tt][1]);
            }
        }

        // p tile: 3-term bf16 split
        {
            float c[4] = {0.f, 0.f, 0.f, 0.f};
#pragma unroll
            for (int s = 0; s < 4; s++) {
                MMA_BF16(c, ah[s], BpH[s]);
                MMA_BF16(c, ah[s], BpL[s]);
                MMA_BF16(c, al[s], BpH[s]);
            }
            const int cp = 8 * w + 2 * t;
            if (node_lo < n) *(float2*)&g_p[(size_t)node_lo * 64 + cp] = make_float2(c[0] + bo0, c[1] + bo1);
            if (node_hi < n) *(float2*)&g_p[(size_t)node_hi * 64 + cp] = make_float2(c[2] + bo0, c[3] + bo1);
        }
    }
}

// ---------------------------------------------------------------------------
// Kernel B: half-warp-per-edge logit + exp + atomic segment sum
// ---------------------------------------------------------------------------
#define EDGES_PER_WARP 8

__global__ void __launch_bounds__(256) edge_kernel(
    const int* __restrict__ src, const int* __restrict__ tgt,
    const float* __restrict__ a_w, const float* __restrict__ a_b, int E)
{
    const int lane = threadIdx.x & 31;
    const int half = lane >> 4;
    const int hl   = lane & 15;
    const int warp = (blockIdx.x * 256 + threadIdx.x) >> 5;

    const float4 aw = *(const float4*)&a_w[4 * hl];
    const float ab = a_b[0];

    const int e0 = warp * EDGES_PER_WARP + half;
#pragma unroll
    for (int i = 0; i < EDGES_PER_WARP / 2; i++) {
        const int e = e0 + 2 * i;
        const bool valid = (e < E);
        const int ee = valid ? e : (E - 1);
        const int s = __ldg(&src[ee]);
        const int t = __ldg(&tgt[ee]);

        const uint2 ur = *(const uint2*)&g_u[(size_t)s * 64 + 4 * hl];
        const uint2 vr = *(const uint2*)&g_v[(size_t)t * 64 + 4 * hl];
        const float2 u0 = __bfloat1622float2(*(const __nv_bfloat162*)&ur.x);
        const float2 u1 = __bfloat1622float2(*(const __nv_bfloat162*)&ur.y);
        const float2 v0 = __bfloat1622float2(*(const __nv_bfloat162*)&vr.x);
        const float2 v1 = __bfloat1622float2(*(const __nv_bfloat162*)&vr.y);

        float part;
        part  = lrelu(u0.x + v0.x) * aw.x;
        part  = fmaf(lrelu(u0.y + v0.y), aw.y, part);
        part  = fmaf(lrelu(u1.x + v1.x), aw.z, part);
        part  = fmaf(lrelu(u1.y + v1.y), aw.w, part);

        part += __shfl_xor_sync(0xffffffffu, part, 8);
        part += __shfl_xor_sync(0xffffffffu, part, 4);
        part += __shfl_xor_sync(0xffffffffu, part, 2);
        part += __shfl_xor_sync(0xffffffffu, part, 1);

        if (hl == 0 && valid) atomicAdd(&g_S[t], __expf(part + ab));
    }
}

// ---------------------------------------------------------------------------
// Kernel C: out = leaky( (S/(S+eps)) * p )
// ---------------------------------------------------------------------------
__global__ void __launch_bounds__(256) finalize_kernel(float* __restrict__ out, int n) {
    const int gid = blockIdx.x * 256 + threadIdx.x;
    if (gid >= n * 16) return;
    const int node = gid >> 4;
    const int j = (gid & 15) << 2;
    const float S = g_S[node];
    const float f = S / (S + 1e-6f);
    float4 p = *(const float4*)&g_p[(size_t)node * 64 + j];
    float4 o;
    o.x = lrelu(f * p.x);
    o.y = lrelu(f * p.y);
    o.z = lrelu(f * p.z);
    o.w = lrelu(f * p.w);
    *(float4*)&out[(size_t)node * 64 + j] = o;
}

// ---------------------------------------------------------------------------
extern "C" void kernel_launch(void* const* d_in, const int* in_sizes, int n_in,
                              void* d_out, int out_size)
{
    const float* x     = (const float*)d_in[0];
    const int*   src   = (const int*)  d_in[1];
    const int*   tgt   = (const int*)  d_in[2];
    const float* W_in  = (const float*)d_in[3];
    const float* b_in  = (const float*)d_in[4];
    const float* a_w   = (const float*)d_in[5];
    const float* a_b   = (const float*)d_in[6];
    const float* W_out = (const float*)d_in[7];
    const float* b_out = (const float*)d_in[8];
    float* out = (float*)d_out;

    const int N = in_sizes[0] / DI;
    const int E = in_sizes[1];

    const int gemm_blocks = (N + 127) / 128;
    precompute_mma<<<gemm_blocks, 256>>>(x, W_in, b_in, W_out, b_out, N);

    const int warps = (E + EDGES_PER_WARP - 1) / EDGES_PER_WARP;
    const int edge_blocks = (warps + 7) / 8;
    edge_kernel<<<edge_blocks, 256>>>(src, tgt, a_w, a_b, E);

    finalize_kernel<<<(N * 16 + 255) / 256, 256>>>(out, N);
}

// round 5
// speedup vs baseline: 3.1920x; 1.4333x over previous
#include <cuda_runtime.h>
#include <cuda_bf16.h>
#include <cuda_fp16.h>
#include <cuda_fp8.h>
#include <cstdint>

// ---------------------------------------------------------------------------
// GAT layer with edge softmax — algebraically reduced + HMMA precompute + fp8
// edge gathers.
//
//   u[n]  = x[n] @ W_in[:64]              (N x 64)   -> fp8 e4m3
//   v[n]  = x[n] @ W_in[64:] + b_in       (N x 64)   -> fp8 e4m3
//   p[n]  = x[n] @ W_out + b_out          (N x 64)   -> fp32 (3-term bf16 split MMA)
//   e     = leaky(u[src]+v[tgt]) . a_w + a_b
//   S[n]  = sum_{tgt=n} exp(e)
//   out[n]= leaky( (S/(S+eps)) * p[n] )
//
// Output depends on the logit path only through (eps/S)*(dS/S), so fp8 u/v is
// numerically free; p needs near-fp32 precision (bf16 hi/lo split).
// ---------------------------------------------------------------------------

#define DI 64
#define NMAX 100000

__device__ unsigned char g_u[(size_t)NMAX * DI];   // fp8 e4m3
__device__ unsigned char g_v[(size_t)NMAX * DI];   // fp8 e4m3
__device__ float g_p[(size_t)NMAX * DI];
__device__ float g_S[NMAX];

__device__ __forceinline__ float lrelu(float x) { return x >= 0.0f ? x : 0.01f * x; }

__device__ __forceinline__ uint32_t smem_u32(const void* p) {
    uint32_t a;
    asm("{ .reg .u64 t; cvta.to.shared.u64 t, %1; cvt.u32.u64 %0, t; }" : "=r"(a) : "l"(p));
    return a;
}

#define MMA_BF16(c, a, b) \
    asm volatile("mma.sync.aligned.m16n8k16.row.col.f32.bf16.bf16.f32 " \
        "{%0,%1,%2,%3}, {%4,%5,%6,%7}, {%8,%9}, {%0,%1,%2,%3};" \
        : "+f"((c)[0]), "+f"((c)[1]), "+f"((c)[2]), "+f"((c)[3]) \
        : "r"((a)[0]), "r"((a)[1]), "r"((a)[2]), "r"((a)[3]), \
          "r"((b)[0]), "r"((b)[1]))

#define LDSM4(r, addr) \
    asm volatile("ldmatrix.sync.aligned.m8n8.x4.shared.b16 {%0,%1,%2,%3}, [%4];" \
        : "=r"((r)[0]), "=r"((r)[1]), "=r"((r)[2]), "=r"((r)[3]) : "r"(addr))

#define A_STRIDE 144
#define A_BYTES  (128 * A_STRIDE)

__device__ __forceinline__ float Wsel(const float* __restrict__ W_in,
                                      const float* __restrict__ W_out, int k, int j) {
    if (j < 64)  return W_in[k * 64 + j];
    if (j < 128) return W_in[(64 + k) * 64 + (j - 64)];
    return W_out[k * 64 + (j - 128)];
}

__device__ __forceinline__ uint32_t pack_bf16x2(float a, float b) {
    __nv_bfloat162 h = __floats2bfloat162_rn(a, b);
    return *(uint32_t*)&h;
}
__device__ __forceinline__ uint16_t pack_fp8x2(float a, float b) {
    return (uint16_t)__nv_cvt_float2_to_fp8x2(make_float2(a, b), __NV_SATFINITE, __NV_E4M3);
}
__device__ __forceinline__ __half2 fp8pair_to_h2(uint32_t w, int hi) {
    __nv_fp8x2_storage_t s2 = (__nv_fp8x2_storage_t)(hi ? (w >> 16) : (w & 0xFFFFu));
    __half2_raw r = __nv_cvt_fp8x2_to_halfraw2(s2, __NV_E4M3);
    return *(__half2*)&r;
}

// ---------------------------------------------------------------------------
// Kernel A: HMMA node GEMM  [N,64] @ [64,192] -> u(fp8) | v(fp8) | p(fp32)
// 128 nodes per CTA, 256 threads (8 warps). Also zeroes g_S.
// ---------------------------------------------------------------------------
__global__ void __launch_bounds__(256, 3) precompute_mma(
    const float* __restrict__ x, const float* __restrict__ W_in,
    const float* __restrict__ b_in, const float* __restrict__ W_out,
    const float* __restrict__ b_out, int n)
{
    __shared__ __align__(16) char smem[2 * A_BYTES];   // A_hi | A_lo
    const uint32_t sb = smem_u32(smem);
    const int tid  = threadIdx.x;
    const int w    = tid >> 5;
    const int lane = tid & 31;
    const int g    = lane >> 2;
    const int t    = lane & 3;
    const int base = blockIdx.x * 128;

    {
        const int zi = blockIdx.x * 256 + tid;
        if (zi < n) g_S[zi] = 0.0f;
    }

    // ---- B fragments in registers ----
    uint32_t Buv[2][4][2];
    uint32_t BpH[4][2], BpL[4][2];
#pragma unroll
    for (int tt = 0; tt < 2; tt++) {
        const int j = 16 * w + 8 * tt + g;
#pragma unroll
        for (int s = 0; s < 4; s++) {
            const int k0 = 16 * s + 2 * t;
            Buv[tt][s][0] = pack_bf16x2(Wsel(W_in, W_out, k0,     j), Wsel(W_in, W_out, k0 + 1, j));
            Buv[tt][s][1] = pack_bf16x2(Wsel(W_in, W_out, k0 + 8, j), Wsel(W_in, W_out, k0 + 9, j));
        }
    }
    {
        const int j = 128 + 8 * w + g;
#pragma unroll
        for (int s = 0; s < 4; s++) {
            const int k0 = 16 * s + 2 * t;
            float f00 = Wsel(W_in, W_out, k0,     j), f01 = Wsel(W_in, W_out, k0 + 1, j);
            float f10 = Wsel(W_in, W_out, k0 + 8, j), f11 = Wsel(W_in, W_out, k0 + 9, j);
            __nv_bfloat16 h00 = __float2bfloat16(f00), h01 = __float2bfloat16(f01);
            __nv_bfloat16 h10 = __float2bfloat16(f10), h11 = __float2bfloat16(f11);
            BpH[s][0] = pack_bf16x2(f00, f01);
            BpH[s][1] = pack_bf16x2(f10, f11);
            BpL[s][0] = pack_bf16x2(f00 - __bfloat162float(h00), f01 - __bfloat162float(h01));
            BpL[s][1] = pack_bf16x2(f10 - __bfloat162float(h10), f11 - __bfloat162float(h11));
        }
    }

    float bv[2][2];
    if (w >= 4) {
#pragma unroll
        for (int tt = 0; tt < 2; tt++) {
            const int jv = 16 * w + 8 * tt + 2 * t - 64;
            bv[tt][0] = b_in[jv]; bv[tt][1] = b_in[jv + 1];
        }
    }
    const float bo0 = b_out[8 * w + 2 * t];
    const float bo1 = b_out[8 * w + 2 * t + 1];

    // ---- stage x tile as bf16 hi/lo into smem ----
    for (int i = tid; i < 128 * 16; i += 256) {
        const int node = i >> 4, kc = i & 15;
        const int gn = base + node;
        float4 xv = make_float4(0.f, 0.f, 0.f, 0.f);
        if (gn < n) xv = *(const float4*)&x[(size_t)gn * 64 + 4 * kc];
        __nv_bfloat16 h0 = __float2bfloat16(xv.x), h1 = __float2bfloat16(xv.y);
        __nv_bfloat16 h2 = __float2bfloat16(xv.z), h3 = __float2bfloat16(xv.w);
        uint2 hi, lo;
        hi.x = pack_bf16x2(xv.x, xv.y);
        hi.y = pack_bf16x2(xv.z, xv.w);
        lo.x = pack_bf16x2(xv.x - __bfloat162float(h0), xv.y - __bfloat162float(h1));
        lo.y = pack_bf16x2(xv.z - __bfloat162float(h2), xv.w - __bfloat162float(h3));
        *(uint2*)(smem + node * A_STRIDE + kc * 8)           = hi;
        *(uint2*)(smem + A_BYTES + node * A_STRIDE + kc * 8) = lo;
    }
    __syncthreads();

    const int lrow = lane & 15;
    const int lcol = (lane >> 4) * 16;

#pragma unroll 1
    for (int mt = 0; mt < 8; mt++) {
        const int m0 = 16 * mt;
        uint32_t ah[4][4], al[4][4];
#pragma unroll
        for (int s = 0; s < 4; s++) {
            const uint32_t off = (uint32_t)((m0 + lrow) * A_STRIDE + 32 * s + lcol);
            LDSM4(ah[s], sb + off);
            LDSM4(al[s], sb + A_BYTES + off);
        }

        const int node_lo = base + m0 + g;
        const int node_hi = node_lo + 8;

#pragma unroll
        for (int tt = 0; tt < 2; tt++) {
            float c[4] = {0.f, 0.f, 0.f, 0.f};
#pragma unroll
            for (int s = 0; s < 4; s++) MMA_BF16(c, ah[s], Buv[tt][s]);
            const int col = 16 * w + 8 * tt + 2 * t;
            if (w < 4) {
                if (node_lo < n) *(uint16_t*)&g_u[(size_t)node_lo * 64 + col] = pack_fp8x2(c[0], c[1]);
                if (node_hi < n) *(uint16_t*)&g_u[(size_t)node_hi * 64 + col] = pack_fp8x2(c[2], c[3]);
            } else {
                const int cv = col - 64;
                if (node_lo < n) *(uint16_t*)&g_v[(size_t)node_lo * 64 + cv] = pack_fp8x2(c[0] + bv[tt][0], c[1] + bv[tt][1]);
                if (node_hi < n) *(uint16_t*)&g_v[(size_t)node_hi * 64 + cv] = pack_fp8x2(c[2] + bv[tt][0], c[3] + bv[tt][1]);
            }
        }

        {
            float c[4] = {0.f, 0.f, 0.f, 0.f};
#pragma unroll
            for (int s = 0; s < 4; s++) {
                MMA_BF16(c, ah[s], BpH[s]);
                MMA_BF16(c, ah[s], BpL[s]);
                MMA_BF16(c, al[s], BpH[s]);
            }
            const int cp = 8 * w + 2 * t;
            if (node_lo < n) *(float2*)&g_p[(size_t)node_lo * 64 + cp] = make_float2(c[0] + bo0, c[1] + bo1);
            if (node_hi < n) *(float2*)&g_p[(size_t)node_hi * 64 + cp] = make_float2(c[2] + bo0, c[3] + bo1);
        }
    }
}

// ---------------------------------------------------------------------------
// Kernel B: 8-lanes-per-edge fp8 logit + exp + atomic segment sum
// Each lane: 8 fp8 from u[src] + 8 fp8 from v[tgt] (8B loads), half2 math,
// 3-step shuffle reduce. 4 edges per warp pass, 16 per warp.
// ---------------------------------------------------------------------------
#define EDGES_PER_WARP 16

__global__ void __launch_bounds__(256) edge_kernel(
    const int* __restrict__ src, const int* __restrict__ tgt,
    const float* __restrict__ a_w, const float* __restrict__ a_b, int E)
{
    const int lane = threadIdx.x & 31;
    const int q  = lane >> 3;      // edge slot within warp pass
    const int sl = lane & 7;       // cols [8*sl, 8*sl+8)
    const int warp = (blockIdx.x * 256 + threadIdx.x) >> 5;

    __half2 aw[4];
#pragma unroll
    for (int pc = 0; pc < 4; pc++)
        aw[pc] = __floats2half2_rn(__ldg(&a_w[8 * sl + 2 * pc]), __ldg(&a_w[8 * sl + 2 * pc + 1]));
    const float ab = a_b[0];
    const __half2 slope = __floats2half2_rn(0.01f, 0.01f);

    const int e0 = warp * EDGES_PER_WARP + q;
#pragma unroll
    for (int i = 0; i < 4; i++) {
        const int e = e0 + 4 * i;
        const bool valid = (e < E);
        const int ee = valid ? e : (E - 1);
        const int s = __ldg(&src[ee]);
        const int t = __ldg(&tgt[ee]);

        const uint2 ur = *(const uint2*)&g_u[(size_t)s * 64 + 8 * sl];
        const uint2 vr = *(const uint2*)&g_v[(size_t)t * 64 + 8 * sl];

        __half2 acc = __floats2half2_rn(0.f, 0.f);
#pragma unroll
        for (int pc = 0; pc < 4; pc++) {
            const uint32_t uw = (pc < 2) ? ur.x : ur.y;
            const uint32_t vw = (pc < 2) ? vr.x : vr.y;
            const int h = pc & 1;
            const __half2 sum = __hadd2(fp8pair_to_h2(uw, h), fp8pair_to_h2(vw, h));
            const __half2 lr  = __hmax2(sum, __hmul2(sum, slope));   // leaky = max(x, 0.01x)
            acc = __hfma2(lr, aw[pc], acc);
        }
        float part = __half2float(__low2half(acc)) + __half2float(__high2half(acc));

        part += __shfl_xor_sync(0xffffffffu, part, 4);
        part += __shfl_xor_sync(0xffffffffu, part, 2);
        part += __shfl_xor_sync(0xffffffffu, part, 1);

        if (sl == 0 && valid) atomicAdd(&g_S[t], __expf(part + ab));
    }
}

// ---------------------------------------------------------------------------
// Kernel C: out = leaky( (S/(S+eps)) * p )
// ---------------------------------------------------------------------------
__global__ void __launch_bounds__(256) finalize_kernel(float* __restrict__ out, int n) {
    const int gid = blockIdx.x * 256 + threadIdx.x;
    if (gid >= n * 16) return;
    const int node = gid >> 4;
    const int j = (gid & 15) << 2;
    const float S = g_S[node];
    const float f = S / (S + 1e-6f);
    float4 p = *(const float4*)&g_p[(size_t)node * 64 + j];
    float4 o;
    o.x = lrelu(f * p.x);
    o.y = lrelu(f * p.y);
    o.z = lrelu(f * p.z);
    o.w = lrelu(f * p.w);
    *(float4*)&out[(size_t)node * 64 + j] = o;
}

// ---------------------------------------------------------------------------
extern "C" void kernel_launch(void* const* d_in, const int* in_sizes, int n_in,
                              void* d_out, int out_size)
{
    const float* x     = (const float*)d_in[0];
    const int*   src   = (const int*)  d_in[1];
    const int*   tgt   = (const int*)  d_in[2];
    const float* W_in  = (const float*)d_in[3];
    const float* b_in  = (const float*)d_in[4];
    const float* a_w   = (const float*)d_in[5];
    const float* a_b   = (const float*)d_in[6];
    const float* W_out = (const float*)d_in[7];
    const float* b_out = (const float*)d_in[8];
    float* out = (float*)d_out;

    const int N = in_sizes[0] / DI;
    const int E = in_sizes[1];

    const int gemm_blocks = (N + 127) / 128;
    precompute_mma<<<gemm_blocks, 256>>>(x, W_in, b_in, W_out, b_out, N);

    const int warps = (E + EDGES_PER_WARP - 1) / EDGES_PER_WARP;
    const int edge_blocks = (warps + 7) / 8;
    edge_kernel<<<edge_blocks, 256>>>(src, tgt, a_w, a_b, E);

    finalize_kernel<<<(N * 16 + 255) / 256, 256>>>(out, N);
}